// round 1
// baseline (speedup 1.0000x reference)
#include <cuda_runtime.h>
#include <cstddef>

// ---------------- problem constants ----------------
#define BATCH   8
#define T_ENC   1024
#define T_DEC   100
#define DMODEL  512
#define NHEAD   8
#define DHEAD   64
#define DFF     2048
#define M_ENC   (BATCH * T_ENC)   // 8192
#define M_DEC   (BATCH * T_DEC)   // 800
#define BHT     (BATCH * NHEAD)   // 64

// ---------------- scratch (device globals; no allocation allowed) ----------------
__device__ float g_q   [M_ENC * DMODEL];
__device__ float g_k   [M_ENC * DMODEL];
__device__ float g_v   [M_ENC * DMODEL];
__device__ float g_att [M_ENC * DMODEL];
__device__ float g_x1  [M_ENC * DMODEL];
__device__ float g_x   [M_ENC * DMODEL];
__device__ float g_h   [M_ENC * DFF];
__device__ float g_scores [BHT * T_ENC * T_ENC];     // 268 MB, biggest buffer
__device__ float g_y1  [M_DEC * DMODEL];
__device__ float g_y2  [M_DEC * DMODEL];
__device__ float g_y   [M_DEC * DMODEL];

// ---------------- generic tiled SGEMM: C = A(MxK) @ B(KxN) (+bias, +relu) ----------------
// BM=BN=64, BK=16, 256 threads, 4x4 per thread. K must be a multiple of 16 (512/2048/64 all are).
__global__ void gemm_kernel(const float* __restrict__ A, const float* __restrict__ B,
                            const float* __restrict__ bias, float* __restrict__ C,
                            int M, int N, int K, int relu) {
    __shared__ float As[16][65];
    __shared__ float Bs[16][65];
    const int tid = threadIdx.x;
    const int tx = tid & 15, ty = tid >> 4;
    const int m0 = blockIdx.y * 64, n0 = blockIdx.x * 64;
    float acc[4][4] = {};

    for (int k0 = 0; k0 < K; k0 += 16) {
        // load A tile 64x16 -> As[k][m]
        #pragma unroll
        for (int i = 0; i < 4; i++) {
            int idx = tid + i * 256;
            int r = idx >> 4, kk = idx & 15;
            int m = m0 + r;
            As[kk][r] = (m < M) ? A[(size_t)m * K + k0 + kk] : 0.f;
        }
        // load B tile 16x64 -> Bs[k][n]
        #pragma unroll
        for (int i = 0; i < 4; i++) {
            int idx = tid + i * 256;
            int kk = idx >> 6, n = idx & 63;
            Bs[kk][n] = (n0 + n < N) ? B[(size_t)(k0 + kk) * N + n0 + n] : 0.f;
        }
        __syncthreads();
        #pragma unroll
        for (int kk = 0; kk < 16; kk++) {
            float a[4], b[4];
            #pragma unroll
            for (int i = 0; i < 4; i++) a[i] = As[kk][ty * 4 + i];
            #pragma unroll
            for (int j = 0; j < 4; j++) b[j] = Bs[kk][tx * 4 + j];
            #pragma unroll
            for (int i = 0; i < 4; i++)
                #pragma unroll
                for (int j = 0; j < 4; j++)
                    acc[i][j] += a[i] * b[j];
        }
        __syncthreads();
    }

    #pragma unroll
    for (int i = 0; i < 4; i++) {
        int m = m0 + ty * 4 + i;
        if (m >= M) continue;
        #pragma unroll
        for (int j = 0; j < 4; j++) {
            int n = n0 + tx * 4 + j;
            if (n >= N) continue;
            float v = acc[i][j];
            if (bias) v += bias[n];
            if (relu) v = fmaxf(v, 0.f);
            C[(size_t)m * N + n] = v;
        }
    }
}

// ---------------- batched attention scores: S[bh,q,k] = scale * <q_bh[q,:], k_bh[k,:]> ----------------
// Q laid out [(b*Tq+q)*512 + h*64 + d], K likewise with Tk. One 64x64 output tile per block, K-dim=64 fully resident.
__global__ void attn_scores_kernel(const float* __restrict__ Q, const float* __restrict__ Kb,
                                   float* __restrict__ S, int Tq, int Tk, float scale) {
    __shared__ float Qs[64][65];
    __shared__ float Ks[64][65];
    const int bh = blockIdx.z;
    const int b = bh >> 3, h = bh & 7;
    const float* qp = Q + (size_t)b * Tq * DMODEL + h * DHEAD;
    const float* kp = Kb + (size_t)b * Tk * DMODEL + h * DHEAD;
    float* sp = S + (size_t)bh * Tq * Tk;
    const int q0 = blockIdx.y * 64, k0 = blockIdx.x * 64;
    const int tid = threadIdx.x;

    #pragma unroll
    for (int i = 0; i < 16; i++) {
        int idx = tid + i * 256;
        int r = idx >> 6, d = idx & 63;
        Qs[r][d] = (q0 + r < Tq) ? qp[(size_t)(q0 + r) * DMODEL + d] : 0.f;
    }
    #pragma unroll
    for (int i = 0; i < 16; i++) {
        int idx = tid + i * 256;
        int r = idx >> 6, d = idx & 63;
        Ks[r][d] = (k0 + r < Tk) ? kp[(size_t)(k0 + r) * DMODEL + d] : 0.f;
    }
    __syncthreads();

    const int tx = tid & 15, ty = tid >> 4;
    float acc[4][4] = {};
    #pragma unroll
    for (int d = 0; d < 64; d++) {
        float a[4], b2[4];
        #pragma unroll
        for (int i = 0; i < 4; i++) a[i] = Qs[ty * 4 + i][d];
        #pragma unroll
        for (int j = 0; j < 4; j++) b2[j] = Ks[tx * 4 + j][d];
        #pragma unroll
        for (int i = 0; i < 4; i++)
            #pragma unroll
            for (int j = 0; j < 4; j++)
                acc[i][j] += a[i] * b2[j];
    }
    #pragma unroll
    for (int i = 0; i < 4; i++) {
        int q = q0 + ty * 4 + i;
        if (q >= Tq) continue;
        #pragma unroll
        for (int j = 0; j < 4; j++) {
            int k = k0 + tx * 4 + j;
            if (k < Tk) sp[(size_t)q * Tk + k] = acc[i][j] * scale;
        }
    }
}

// ---------------- row softmax (+ faithful post-softmax causal fill of -1e10) ----------------
__global__ void softmax_kernel(float* __restrict__ S, int Tq, int Tk, int causal) {
    const int q = blockIdx.x;
    const int bh = blockIdx.y;
    float* row = S + ((size_t)bh * Tq + q) * Tk;
    __shared__ float red[256];
    const int tid = threadIdx.x;

    float m = -1e30f;
    for (int k = tid; k < Tk; k += 256) m = fmaxf(m, row[k]);
    red[tid] = m; __syncthreads();
    for (int s = 128; s > 0; s >>= 1) { if (tid < s) red[tid] = fmaxf(red[tid], red[tid + s]); __syncthreads(); }
    m = red[0]; __syncthreads();

    float sum = 0.f;
    for (int k = tid; k < Tk; k += 256) { float e = expf(row[k] - m); row[k] = e; sum += e; }
    red[tid] = sum; __syncthreads();
    for (int s = 128; s > 0; s >>= 1) { if (tid < s) red[tid] += red[tid + s]; __syncthreads(); }
    const float inv = 1.f / red[0];

    for (int k = tid; k < Tk; k += 256) {
        float p = row[k] * inv;
        if (causal && k > q) p = -1e10f;   // reference masks AFTER softmax with -1e10
        row[k] = p;
    }
}

// ---------------- batched P @ V: O[(b*Tq+q)*512 + h*64 + d] ----------------
__global__ void attn_pv_kernel(const float* __restrict__ P, const float* __restrict__ V,
                               float* __restrict__ O, int Tq, int Tk) {
    __shared__ float Ps[64][33];
    __shared__ float Vs[32][65];
    const int bh = blockIdx.z;
    const int b = bh >> 3, h = bh & 7;
    const float* pp = P + (size_t)bh * Tq * Tk;
    const float* vp = V + (size_t)b * Tk * DMODEL + h * DHEAD;
    const int q0 = blockIdx.y * 64;
    const int tid = threadIdx.x;
    const int tx = tid & 15, ty = tid >> 4;
    float acc[4][4] = {};

    for (int k0 = 0; k0 < Tk; k0 += 32) {
        #pragma unroll
        for (int i = 0; i < 8; i++) {
            int idx = tid + i * 256;
            int r = idx >> 5, kk = idx & 31;
            int q = q0 + r, k = k0 + kk;
            Ps[r][kk] = (q < Tq && k < Tk) ? pp[(size_t)q * Tk + k] : 0.f;
        }
        #pragma unroll
        for (int i = 0; i < 8; i++) {
            int idx = tid + i * 256;
            int kk = idx >> 6, d = idx & 63;
            int k = k0 + kk;
            Vs[kk][d] = (k < Tk) ? vp[(size_t)k * DMODEL + d] : 0.f;
        }
        __syncthreads();
        #pragma unroll
        for (int kk = 0; kk < 32; kk++) {
            float a[4], b2[4];
            #pragma unroll
            for (int i = 0; i < 4; i++) a[i] = Ps[ty * 4 + i][kk];
            #pragma unroll
            for (int j = 0; j < 4; j++) b2[j] = Vs[kk][tx * 4 + j];
            #pragma unroll
            for (int i = 0; i < 4; i++)
                #pragma unroll
                for (int j = 0; j < 4; j++)
                    acc[i][j] += a[i] * b2[j];
        }
        __syncthreads();
    }

    #pragma unroll
    for (int i = 0; i < 4; i++) {
        int q = q0 + ty * 4 + i;
        if (q >= Tq) continue;
        #pragma unroll
        for (int j = 0; j < 4; j++)
            O[(size_t)(b * Tq + q) * DMODEL + h * DHEAD + tx * 4 + j] = acc[i][j];
    }
}

// ---------------- fused residual + LayerNorm over D=512 ----------------
__global__ void ln_res_kernel(const float* __restrict__ A, const float* __restrict__ Bv,
                              const float* __restrict__ g, const float* __restrict__ be,
                              float* __restrict__ O) {
    const int row = blockIdx.x;
    const float* a = A + (size_t)row * DMODEL;
    const float* b = Bv + (size_t)row * DMODEL;
    __shared__ float red[256];
    const int tid = threadIdx.x;

    float v0 = a[tid] + b[tid];
    float v1 = a[tid + 256] + b[tid + 256];

    red[tid] = v0 + v1; __syncthreads();
    for (int s = 128; s > 0; s >>= 1) { if (tid < s) red[tid] += red[tid + s]; __syncthreads(); }
    const float mean = red[0] * (1.f / DMODEL); __syncthreads();

    float d0 = v0 - mean, d1 = v1 - mean;
    red[tid] = d0 * d0 + d1 * d1; __syncthreads();
    for (int s = 128; s > 0; s >>= 1) { if (tid < s) red[tid] += red[tid + s]; __syncthreads(); }
    const float inv = rsqrtf(red[0] * (1.f / DMODEL) + 1e-5f);

    O[(size_t)row * DMODEL + tid]       = d0 * inv * g[tid]       + be[tid];
    O[(size_t)row * DMODEL + tid + 256] = d1 * inv * g[tid + 256] + be[tid + 256];
}

// ---------------- host orchestration ----------------
static inline void gemm(const float* A, const float* B, const float* bias, float* C,
                        int M, int N, int K, int relu) {
    dim3 grid((N + 63) / 64, (M + 63) / 64);
    gemm_kernel<<<grid, 256>>>(A, B, bias, C, M, N, K, relu);
}

template <typename T>
static inline float* sym(T& s) {
    void* p = nullptr;
    cudaGetSymbolAddress(&p, s);
    return (float*)p;
}

extern "C" void kernel_launch(void* const* d_in, const int* in_sizes, int n_in,
                              void* d_out, int out_size) {
    (void)in_sizes; (void)n_in; (void)out_size;
    const float* x_in      = (const float*)d_in[0];
    const float* y_in      = (const float*)d_in[1];
    const float* enc_Wq    = (const float*)d_in[2];
    const float* enc_Wk    = (const float*)d_in[3];
    const float* enc_Wv    = (const float*)d_in[4];
    const float* enc_ff_w1 = (const float*)d_in[5];
    const float* enc_ff_b1 = (const float*)d_in[6];
    const float* enc_ff_w2 = (const float*)d_in[7];
    const float* enc_ff_b2 = (const float*)d_in[8];
    const float* enc_ln1_g = (const float*)d_in[9];
    const float* enc_ln1_b = (const float*)d_in[10];
    const float* enc_ln2_g = (const float*)d_in[11];
    const float* enc_ln2_b = (const float*)d_in[12];
    const float* dec_Wq1   = (const float*)d_in[13];
    const float* dec_Wk1   = (const float*)d_in[14];
    const float* dec_Wv1   = (const float*)d_in[15];
    const float* dec_Wq2   = (const float*)d_in[16];
    const float* dec_Wk2   = (const float*)d_in[17];
    const float* dec_Wv2   = (const float*)d_in[18];
    const float* dec_ff_w1 = (const float*)d_in[19];
    const float* dec_ff_b1 = (const float*)d_in[20];
    const float* dec_ff_w2 = (const float*)d_in[21];
    const float* dec_ff_b2 = (const float*)d_in[22];
    const float* dec_ln1_g = (const float*)d_in[23];
    const float* dec_ln1_b = (const float*)d_in[24];
    const float* dec_ln2_g = (const float*)d_in[25];
    const float* dec_ln2_b = (const float*)d_in[26];
    const float* dec_ln3_g = (const float*)d_in[27];
    const float* dec_ln3_b = (const float*)d_in[28];

    float* q   = sym(g_q);
    float* k   = sym(g_k);
    float* v   = sym(g_v);
    float* att = sym(g_att);
    float* x1  = sym(g_x1);
    float* gx  = sym(g_x);
    float* h   = sym(g_h);
    float* sc  = sym(g_scores);
    float* y1  = sym(g_y1);
    float* y2  = sym(g_y2);
    float* gy  = sym(g_y);

    const float scale = 0.125f;  // 1/sqrt(64)
    const int WO = DMODEL * DMODEL;      // 262144, per-layer weight stride (D x H*DK)
    const int FO1 = DMODEL * DFF;        // w1 stride
    const int FO2 = DFF * DMODEL;        // w2 stride

    // -------- encoder --------
    const float* xc = x_in;
    for (int i = 0; i < 2; i++) {
        gemm(xc, enc_Wq + (size_t)i * WO, nullptr, q, M_ENC, DMODEL, DMODEL, 0);
        gemm(xc, enc_Wk + (size_t)i * WO, nullptr, k, M_ENC, DMODEL, DMODEL, 0);
        gemm(xc, enc_Wv + (size_t)i * WO, nullptr, v, M_ENC, DMODEL, DMODEL, 0);
        attn_scores_kernel<<<dim3(16, 16, BHT), 256>>>(q, k, sc, T_ENC, T_ENC, scale);
        softmax_kernel<<<dim3(T_ENC, BHT), 256>>>(sc, T_ENC, T_ENC, 0);
        attn_pv_kernel<<<dim3(1, 16, BHT), 256>>>(sc, v, att, T_ENC, T_ENC);
        ln_res_kernel<<<M_ENC, 256>>>(xc, att, enc_ln1_g + i * DMODEL, enc_ln1_b + i * DMODEL, x1);
        gemm(x1, enc_ff_w1 + (size_t)i * FO1, enc_ff_b1 + i * DFF, h, M_ENC, DFF, DMODEL, 1);
        gemm(h, enc_ff_w2 + (size_t)i * FO2, enc_ff_b2 + i * DMODEL, att, M_ENC, DMODEL, DFF, 0);
        ln_res_kernel<<<M_ENC, 256>>>(x1, att, enc_ln2_g + i * DMODEL, enc_ln2_b + i * DMODEL, gx);
        xc = gx;
    }

    // -------- decoder --------
    const float* yc = y_in;
    for (int i = 0; i < 2; i++) {
        // masked self-attention (mask applied AFTER softmax, fill -1e10, faithful to ref)
        gemm(yc, dec_Wq1 + (size_t)i * WO, nullptr, q, M_DEC, DMODEL, DMODEL, 0);
        gemm(yc, dec_Wk1 + (size_t)i * WO, nullptr, k, M_DEC, DMODEL, DMODEL, 0);
        gemm(yc, dec_Wv1 + (size_t)i * WO, nullptr, v, M_DEC, DMODEL, DMODEL, 0);
        attn_scores_kernel<<<dim3(2, 2, BHT), 256>>>(q, k, sc, T_DEC, T_DEC, scale);
        softmax_kernel<<<dim3(T_DEC, BHT), 256>>>(sc, T_DEC, T_DEC, 1);
        attn_pv_kernel<<<dim3(1, 2, BHT), 256>>>(sc, v, att, T_DEC, T_DEC);
        ln_res_kernel<<<M_DEC, 256>>>(yc, att, dec_ln1_g + i * DMODEL, dec_ln1_b + i * DMODEL, y1);

        // cross-attention against encoder output xc
        gemm(y1, dec_Wq2 + (size_t)i * WO, nullptr, q, M_DEC, DMODEL, DMODEL, 0);
        gemm(xc, dec_Wk2 + (size_t)i * WO, nullptr, k, M_ENC, DMODEL, DMODEL, 0);
        gemm(xc, dec_Wv2 + (size_t)i * WO, nullptr, v, M_ENC, DMODEL, DMODEL, 0);
        attn_scores_kernel<<<dim3(16, 2, BHT), 256>>>(q, k, sc, T_DEC, T_ENC, scale);
        softmax_kernel<<<dim3(T_DEC, BHT), 256>>>(sc, T_DEC, T_ENC, 0);
        attn_pv_kernel<<<dim3(1, 2, BHT), 256>>>(sc, v, att, T_DEC, T_ENC);
        ln_res_kernel<<<M_DEC, 256>>>(y1, att, dec_ln2_g + i * DMODEL, dec_ln2_b + i * DMODEL, y2);

        // feed-forward
        gemm(y2, dec_ff_w1 + (size_t)i * FO1, dec_ff_b1 + i * DFF, h, M_DEC, DFF, DMODEL, 1);
        gemm(h, dec_ff_w2 + (size_t)i * FO2, dec_ff_b2 + i * DMODEL, att, M_DEC, DMODEL, DFF, 0);
        float* outp = (i == 1) ? (float*)d_out : gy;
        ln_res_kernel<<<M_DEC, 256>>>(y2, att, dec_ln3_g + i * DMODEL, dec_ln3_b + i * DMODEL, outp);
        yc = gy;
    }
}

// round 2
// speedup vs baseline: 1.4689x; 1.4689x over previous
#include <cuda_runtime.h>
#include <cstdint>
#include <cstddef>

// ---------------- problem constants ----------------
#define BATCH   8
#define T_ENC   1024
#define T_DEC   100
#define DMODEL  512
#define NHEAD   8
#define DHEAD   64
#define DFF     2048
#define M_ENC   (BATCH * T_ENC)   // 8192
#define M_DEC   (BATCH * T_DEC)   // 800
#define BHT     (BATCH * NHEAD)   // 64

// ---------------- scratch (device globals; no allocation allowed) ----------------
__device__ float g_q   [M_ENC * DMODEL];
__device__ float g_k   [M_ENC * DMODEL];
__device__ float g_v   [M_ENC * DMODEL];
__device__ float g_att [M_ENC * DMODEL];
__device__ float g_x1  [M_ENC * DMODEL];
__device__ float g_x   [M_ENC * DMODEL];
__device__ float g_h   [M_ENC * DFF];
__device__ float g_scores [BHT * T_ENC * T_ENC];
__device__ float g_y1  [M_DEC * DMODEL];
__device__ float g_y2  [M_DEC * DMODEL];
__device__ float g_y   [M_DEC * DMODEL];

// ================= tf32 MMA GEMM =================
// C[z] = alpha * A[z](MxK) @ B[z](KxN) (+bias) (+relu)
// Block tile 128x128x32, 256 threads (8 warps: 2 in M x 4 in N), warp tile 64x32.
// mma.sync.aligned.m16n8k8 tf32. Batched via blockIdx.z with split strides
// (z = zo*8 + zi) so (batch, head) offsets compose.

#define BM 128
#define BN 128
#define BKT 32

__device__ __forceinline__ uint32_t f2tf32(float x) {
    uint32_t t;
    asm("cvt.rna.tf32.f32 %0, %1;" : "=r"(t) : "f"(x));
    return t;
}

template<bool TRANSB, int RELU>
__global__ __launch_bounds__(256)
void mma_gemm(const float* __restrict__ A, const float* __restrict__ B,
              const float* __restrict__ bias, float* __restrict__ C,
              int M, int N, int K,
              int lda, int ldb, int ldc,
              long long sAo, long long sAi, long long sBo, long long sBi,
              long long sCo, long long sCi, float alpha)
{
    const int z = blockIdx.z;
    const long long zo = z >> 3, zi = z & 7;
    A += zo * sAo + zi * sAi;
    B += zo * sBo + zi * sBi;
    C += zo * sCo + zi * sCi;

    // A in m-major [m][k] stride 36: fragment banks = 4g+tig (conflict-free)
    __shared__ __align__(16) uint32_t As[BM][BKT + 4];
    // B: TRANSB -> n-major [n][k] stride 36 ; else k-major [k][n] stride 132
    __shared__ __align__(16) uint32_t Bsm[TRANSB ? BN * (BKT + 4) : BKT * (BN + 4)];

    const int tid  = threadIdx.x;
    const int wid  = tid >> 5, lane = tid & 31;
    const int wm   = wid & 1;        // 0..1 (M)
    const int wn   = wid >> 1;       // 0..3 (N)
    const int g    = lane >> 2;      // groupID 0..7
    const int tig  = lane & 3;       // thread-in-group 0..3
    const int m0   = blockIdx.y * BM, n0 = blockIdx.x * BN;

    float acc[4][4][4];
    #pragma unroll
    for (int i = 0; i < 4; i++)
        #pragma unroll
        for (int j = 0; j < 4; j++)
            #pragma unroll
            for (int c = 0; c < 4; c++) acc[i][j][c] = 0.f;

    for (int k0 = 0; k0 < K; k0 += BKT) {
        // ---- load A tile: 128 x 32, float4 along k (K,lda always %4==0) ----
        #pragma unroll
        for (int i = 0; i < 4; i++) {
            int idx = tid + (i << 8);          // 0..1023
            int r = idx >> 3, kk4 = idx & 7;
            int m = m0 + r, k = k0 + (kk4 << 2);
            uint4 out;
            if (m < M && k + 3 < K) {
                float4 v = *(const float4*)(A + (size_t)m * lda + k);
                out.x = f2tf32(v.x); out.y = f2tf32(v.y);
                out.z = f2tf32(v.z); out.w = f2tf32(v.w);
            } else if (m < M && k < K) {   // unreachable given K%4==0, kept safe
                float4 v = {0,0,0,0};
                const float* ap = A + (size_t)m * lda;
                if (k + 0 < K) v.x = ap[k + 0];
                if (k + 1 < K) v.y = ap[k + 1];
                if (k + 2 < K) v.z = ap[k + 2];
                if (k + 3 < K) v.w = ap[k + 3];
                out.x = f2tf32(v.x); out.y = f2tf32(v.y);
                out.z = f2tf32(v.z); out.w = f2tf32(v.w);
            } else {
                out = make_uint4(0, 0, 0, 0);
            }
            *(uint4*)&As[r][kk4 << 2] = out;
        }
        // ---- load B tile ----
        if (TRANSB) {
            // B is N x K row-major; store n-major [n][k] stride 36
            #pragma unroll
            for (int i = 0; i < 4; i++) {
                int idx = tid + (i << 8);
                int r = idx >> 3, kk4 = idx & 7;
                int n = n0 + r, k = k0 + (kk4 << 2);
                uint4 out;
                if (n < N && k + 3 < K) {
                    float4 v = *(const float4*)(B + (size_t)n * ldb + k);
                    out.x = f2tf32(v.x); out.y = f2tf32(v.y);
                    out.z = f2tf32(v.z); out.w = f2tf32(v.w);
                } else {
                    out = make_uint4(0, 0, 0, 0);
                }
                *(uint4*)&Bsm[r * (BKT + 4) + (kk4 << 2)] = out;
            }
        } else {
            // B is K x N row-major; store k-major [k][n] stride 132
            #pragma unroll
            for (int i = 0; i < 4; i++) {
                int idx = tid + (i << 8);
                int kk = idx >> 5, n4 = idx & 31;
                int k = k0 + kk, n = n0 + (n4 << 2);
                uint4 out;
                if (k < K && n + 3 < N) {
                    float4 v = *(const float4*)(B + (size_t)k * ldb + n);
                    out.x = f2tf32(v.x); out.y = f2tf32(v.y);
                    out.z = f2tf32(v.z); out.w = f2tf32(v.w);
                } else if (k < K && n < N) {
                    float4 v = {0,0,0,0};
                    const float* bp = B + (size_t)k * ldb;
                    if (n + 0 < N) v.x = bp[n + 0];
                    if (n + 1 < N) v.y = bp[n + 1];
                    if (n + 2 < N) v.z = bp[n + 2];
                    if (n + 3 < N) v.w = bp[n + 3];
                    out.x = f2tf32(v.x); out.y = f2tf32(v.y);
                    out.z = f2tf32(v.z); out.w = f2tf32(v.w);
                } else {
                    out = make_uint4(0, 0, 0, 0);
                }
                *(uint4*)&Bsm[kk * (BN + 4) + (n4 << 2)] = out;
            }
        }
        __syncthreads();

        // ---- compute: 4 k-steps of 8 ----
        #pragma unroll
        for (int ks = 0; ks < BKT; ks += 8) {
            uint32_t af[4][4];
            #pragma unroll
            for (int mi = 0; mi < 4; mi++) {
                int mr = wm * 64 + mi * 16;
                af[mi][0] = As[mr + g    ][ks + tig    ];
                af[mi][1] = As[mr + g + 8][ks + tig    ];
                af[mi][2] = As[mr + g    ][ks + tig + 4];
                af[mi][3] = As[mr + g + 8][ks + tig + 4];
            }
            uint32_t bf[4][2];
            #pragma unroll
            for (int ni = 0; ni < 4; ni++) {
                int nc = wn * 32 + ni * 8 + g;
                if (TRANSB) {
                    bf[ni][0] = Bsm[nc * (BKT + 4) + ks + tig    ];
                    bf[ni][1] = Bsm[nc * (BKT + 4) + ks + tig + 4];
                } else {
                    bf[ni][0] = Bsm[(ks + tig    ) * (BN + 4) + nc];
                    bf[ni][1] = Bsm[(ks + tig + 4) * (BN + 4) + nc];
                }
            }
            #pragma unroll
            for (int mi = 0; mi < 4; mi++)
                #pragma unroll
                for (int ni = 0; ni < 4; ni++) {
                    asm volatile(
                        "mma.sync.aligned.m16n8k8.row.col.f32.tf32.tf32.f32 "
                        "{%0,%1,%2,%3}, {%4,%5,%6,%7}, {%8,%9}, {%0,%1,%2,%3};"
                        : "+f"(acc[mi][ni][0]), "+f"(acc[mi][ni][1]),
                          "+f"(acc[mi][ni][2]), "+f"(acc[mi][ni][3])
                        : "r"(af[mi][0]), "r"(af[mi][1]), "r"(af[mi][2]), "r"(af[mi][3]),
                          "r"(bf[ni][0]), "r"(bf[ni][1]));
                }
        }
        __syncthreads();
    }

    // ---- epilogue ----
    #pragma unroll
    for (int mi = 0; mi < 4; mi++) {
        int mb = m0 + wm * 64 + mi * 16;
        #pragma unroll
        for (int ni = 0; ni < 4; ni++) {
            int nb = n0 + wn * 32 + ni * 8 + 2 * tig;
            #pragma unroll
            for (int c = 0; c < 4; c++) {
                int m = mb + g + ((c & 2) ? 8 : 0);
                int n = nb + (c & 1);
                if (m < M && n < N) {
                    float v = alpha * acc[mi][ni][c];
                    if (bias) v += bias[n];
                    if (RELU) v = fmaxf(v, 0.f);
                    C[(size_t)m * ldc + n] = v;
                }
            }
        }
    }
}

// ---------------- fp32 attention kernels (decoder self-attention only) ----------------
__global__ void attn_scores_kernel(const float* __restrict__ Q, const float* __restrict__ Kb,
                                   float* __restrict__ S, int Tq, int Tk, float scale) {
    __shared__ float Qs[64][65];
    __shared__ float Ks[64][65];
    const int bh = blockIdx.z;
    const int b = bh >> 3, h = bh & 7;
    const float* qp = Q + (size_t)b * Tq * DMODEL + h * DHEAD;
    const float* kp = Kb + (size_t)b * Tk * DMODEL + h * DHEAD;
    float* sp = S + (size_t)bh * Tq * Tk;
    const int q0 = blockIdx.y * 64, k0 = blockIdx.x * 64;
    const int tid = threadIdx.x;

    #pragma unroll
    for (int i = 0; i < 16; i++) {
        int idx = tid + i * 256;
        int r = idx >> 6, d = idx & 63;
        Qs[r][d] = (q0 + r < Tq) ? qp[(size_t)(q0 + r) * DMODEL + d] : 0.f;
    }
    #pragma unroll
    for (int i = 0; i < 16; i++) {
        int idx = tid + i * 256;
        int r = idx >> 6, d = idx & 63;
        Ks[r][d] = (k0 + r < Tk) ? kp[(size_t)(k0 + r) * DMODEL + d] : 0.f;
    }
    __syncthreads();

    const int tx = tid & 15, ty = tid >> 4;
    float acc[4][4] = {};
    #pragma unroll
    for (int d = 0; d < 64; d++) {
        float a[4], b2[4];
        #pragma unroll
        for (int i = 0; i < 4; i++) a[i] = Qs[ty * 4 + i][d];
        #pragma unroll
        for (int j = 0; j < 4; j++) b2[j] = Ks[tx * 4 + j][d];
        #pragma unroll
        for (int i = 0; i < 4; i++)
            #pragma unroll
            for (int j = 0; j < 4; j++)
                acc[i][j] += a[i] * b2[j];
    }
    #pragma unroll
    for (int i = 0; i < 4; i++) {
        int q = q0 + ty * 4 + i;
        if (q >= Tq) continue;
        #pragma unroll
        for (int j = 0; j < 4; j++) {
            int k = k0 + tx * 4 + j;
            if (k < Tk) sp[(size_t)q * Tk + k] = acc[i][j] * scale;
        }
    }
}

__global__ void attn_pv_kernel(const float* __restrict__ P, const float* __restrict__ V,
                               float* __restrict__ O, int Tq, int Tk) {
    __shared__ float Ps[64][33];
    __shared__ float Vs[32][65];
    const int bh = blockIdx.z;
    const int b = bh >> 3, h = bh & 7;
    const float* pp = P + (size_t)bh * Tq * Tk;
    const float* vp = V + (size_t)b * Tk * DMODEL + h * DHEAD;
    const int q0 = blockIdx.y * 64;
    const int tid = threadIdx.x;
    const int tx = tid & 15, ty = tid >> 4;
    float acc[4][4] = {};

    for (int k0 = 0; k0 < Tk; k0 += 32) {
        #pragma unroll
        for (int i = 0; i < 8; i++) {
            int idx = tid + i * 256;
            int r = idx >> 5, kk = idx & 31;
            int q = q0 + r, k = k0 + kk;
            Ps[r][kk] = (q < Tq && k < Tk) ? pp[(size_t)q * Tk + k] : 0.f;
        }
        #pragma unroll
        for (int i = 0; i < 8; i++) {
            int idx = tid + i * 256;
            int kk = idx >> 6, d = idx & 63;
            int k = k0 + kk;
            Vs[kk][d] = (k < Tk) ? vp[(size_t)k * DMODEL + d] : 0.f;
        }
        __syncthreads();
        #pragma unroll
        for (int kk = 0; kk < 32; kk++) {
            float a[4], b2[4];
            #pragma unroll
            for (int i = 0; i < 4; i++) a[i] = Ps[ty * 4 + i][kk];
            #pragma unroll
            for (int j = 0; j < 4; j++) b2[j] = Vs[kk][tx * 4 + j];
            #pragma unroll
            for (int i = 0; i < 4; i++)
                #pragma unroll
                for (int j = 0; j < 4; j++)
                    acc[i][j] += a[i] * b2[j];
        }
        __syncthreads();
    }

    #pragma unroll
    for (int i = 0; i < 4; i++) {
        int q = q0 + ty * 4 + i;
        if (q >= Tq) continue;
        #pragma unroll
        for (int j = 0; j < 4; j++)
            O[(size_t)(b * Tq + q) * DMODEL + h * DHEAD + tx * 4 + j] = acc[i][j];
    }
}

// ---------------- register-resident softmax (2 memory passes) ----------------
// Tk <= 1024. Post-softmax causal fill of -1e10, faithful to reference.
__global__ void softmax_kernel(float* __restrict__ S, int Tq, int Tk, int causal) {
    const int q = blockIdx.x, bh = blockIdx.y, tid = threadIdx.x;
    float* row = S + ((size_t)bh * Tq + q) * Tk;
    __shared__ float redm[8];
    __shared__ float reds[8];

    float r[4];
    float m = -1e30f;
    #pragma unroll
    for (int i = 0; i < 4; i++) {
        int k = tid + (i << 8);
        r[i] = (k < Tk) ? row[k] : -1e30f;
        m = fmaxf(m, r[i]);
    }
    #pragma unroll
    for (int o = 16; o; o >>= 1) m = fmaxf(m, __shfl_xor_sync(0xffffffffu, m, o));
    if ((tid & 31) == 0) redm[tid >> 5] = m;
    __syncthreads();
    m = redm[0];
    #pragma unroll
    for (int i = 1; i < 8; i++) m = fmaxf(m, redm[i]);

    float s = 0.f;
    #pragma unroll
    for (int i = 0; i < 4; i++) {
        r[i] = expf(r[i] - m);
        s += r[i];
    }
    #pragma unroll
    for (int o = 16; o; o >>= 1) s += __shfl_xor_sync(0xffffffffu, s, o);
    if ((tid & 31) == 0) reds[tid >> 5] = s;
    __syncthreads();
    s = 0.f;
    #pragma unroll
    for (int i = 0; i < 8; i++) s += reds[i];
    const float inv = 1.f / s;

    #pragma unroll
    for (int i = 0; i < 4; i++) {
        int k = tid + (i << 8);
        if (k < Tk) {
            float p = r[i] * inv;
            if (causal && k > q) p = -1e10f;
            row[k] = p;
        }
    }
}

// ---------------- fused residual + LayerNorm over D=512 ----------------
__global__ void ln_res_kernel(const float* __restrict__ A, const float* __restrict__ Bv,
                              const float* __restrict__ g, const float* __restrict__ be,
                              float* __restrict__ O) {
    const int row = blockIdx.x;
    const float* a = A + (size_t)row * DMODEL;
    const float* b = Bv + (size_t)row * DMODEL;
    __shared__ float red[256];
    const int tid = threadIdx.x;

    float v0 = a[tid] + b[tid];
    float v1 = a[tid + 256] + b[tid + 256];

    red[tid] = v0 + v1; __syncthreads();
    for (int s = 128; s > 0; s >>= 1) { if (tid < s) red[tid] += red[tid + s]; __syncthreads(); }
    const float mean = red[0] * (1.f / DMODEL); __syncthreads();

    float d0 = v0 - mean, d1 = v1 - mean;
    red[tid] = d0 * d0 + d1 * d1; __syncthreads();
    for (int s = 128; s > 0; s >>= 1) { if (tid < s) red[tid] += red[tid + s]; __syncthreads(); }
    const float inv = rsqrtf(red[0] * (1.f / DMODEL) + 1e-5f);

    O[(size_t)row * DMODEL + tid]       = d0 * inv * g[tid]       + be[tid];
    O[(size_t)row * DMODEL + tid + 256] = d1 * inv * g[tid + 256] + be[tid + 256];
}

// ---------------- host orchestration ----------------
static inline void mgemm(const float* A, const float* B, const float* bias, float* C,
                         int M, int N, int K, int lda, int ldb, int ldc,
                         long long sAo, long long sAi, long long sBo, long long sBi,
                         long long sCo, long long sCi, int batch, float alpha,
                         bool transb, int relu) {
    dim3 grid((N + BN - 1) / BN, (M + BM - 1) / BM, batch);
    if (transb)
        mma_gemm<true, 0><<<grid, 256>>>(A, B, bias, C, M, N, K, lda, ldb, ldc,
                                         sAo, sAi, sBo, sBi, sCo, sCi, alpha);
    else if (relu)
        mma_gemm<false, 1><<<grid, 256>>>(A, B, bias, C, M, N, K, lda, ldb, ldc,
                                          sAo, sAi, sBo, sBi, sCo, sCi, alpha);
    else
        mma_gemm<false, 0><<<grid, 256>>>(A, B, bias, C, M, N, K, lda, ldb, ldc,
                                          sAo, sAi, sBo, sBi, sCo, sCi, alpha);
}

template <typename T>
static inline float* sym(T& s) {
    void* p = nullptr;
    cudaGetSymbolAddress(&p, s);
    return (float*)p;
}

extern "C" void kernel_launch(void* const* d_in, const int* in_sizes, int n_in,
                              void* d_out, int out_size) {
    (void)in_sizes; (void)n_in; (void)out_size;
    const float* x_in      = (const float*)d_in[0];
    const float* y_in      = (const float*)d_in[1];
    const float* enc_Wq    = (const float*)d_in[2];
    const float* enc_Wk    = (const float*)d_in[3];
    const float* enc_Wv    = (const float*)d_in[4];
    const float* enc_ff_w1 = (const float*)d_in[5];
    const float* enc_ff_b1 = (const float*)d_in[6];
    const float* enc_ff_w2 = (const float*)d_in[7];
    const float* enc_ff_b2 = (const float*)d_in[8];
    const float* enc_ln1_g = (const float*)d_in[9];
    const float* enc_ln1_b = (const float*)d_in[10];
    const float* enc_ln2_g = (const float*)d_in[11];
    const float* enc_ln2_b = (const float*)d_in[12];
    const float* dec_Wq1   = (const float*)d_in[13];
    const float* dec_Wk1   = (const float*)d_in[14];
    const float* dec_Wv1   = (const float*)d_in[15];
    const float* dec_Wq2   = (const float*)d_in[16];
    const float* dec_Wk2   = (const float*)d_in[17];
    const float* dec_Wv2   = (const float*)d_in[18];
    const float* dec_ff_w1 = (const float*)d_in[19];
    const float* dec_ff_b1 = (const float*)d_in[20];
    const float* dec_ff_w2 = (const float*)d_in[21];
    const float* dec_ff_b2 = (const float*)d_in[22];
    const float* dec_ln1_g = (const float*)d_in[23];
    const float* dec_ln1_b = (const float*)d_in[24];
    const float* dec_ln2_g = (const float*)d_in[25];
    const float* dec_ln2_b = (const float*)d_in[26];
    const float* dec_ln3_g = (const float*)d_in[27];
    const float* dec_ln3_b = (const float*)d_in[28];

    float* q   = sym(g_q);
    float* k   = sym(g_k);
    float* v   = sym(g_v);
    float* att = sym(g_att);
    float* x1  = sym(g_x1);
    float* gx  = sym(g_x);
    float* h   = sym(g_h);
    float* sc  = sym(g_scores);
    float* y1  = sym(g_y1);
    float* y2  = sym(g_y2);
    float* gy  = sym(g_y);

    const float scale = 0.125f;  // 1/sqrt(64)
    const long long WO = DMODEL * DMODEL;
    const long long FO1 = DMODEL * DFF;
    const long long FO2 = DFF * DMODEL;

    // -------- encoder --------
    const float* xc = x_in;
    for (int i = 0; i < 2; i++) {
        mgemm(xc, enc_Wq + i * WO, nullptr, q, M_ENC, DMODEL, DMODEL, DMODEL, DMODEL, DMODEL,
              0,0,0,0,0,0, 1, 1.f, false, 0);
        mgemm(xc, enc_Wk + i * WO, nullptr, k, M_ENC, DMODEL, DMODEL, DMODEL, DMODEL, DMODEL,
              0,0,0,0,0,0, 1, 1.f, false, 0);
        mgemm(xc, enc_Wv + i * WO, nullptr, v, M_ENC, DMODEL, DMODEL, DMODEL, DMODEL, DMODEL,
              0,0,0,0,0,0, 1, 1.f, false, 0);
        // scores = scale * Q @ K^T, batched over 64 (b,h)
        mgemm(q, k, nullptr, sc, T_ENC, T_ENC, DHEAD, DMODEL, DMODEL, T_ENC,
              (long long)T_ENC * DMODEL, DHEAD,
              (long long)T_ENC * DMODEL, DHEAD,
              8LL * T_ENC * T_ENC, (long long)T_ENC * T_ENC,
              BHT, scale, true, 0);
        softmax_kernel<<<dim3(T_ENC, BHT), 256>>>(sc, T_ENC, T_ENC, 0);
        // att = P @ V
        mgemm(sc, v, nullptr, att, T_ENC, DHEAD, T_ENC, T_ENC, DMODEL, DMODEL,
              8LL * T_ENC * T_ENC, (long long)T_ENC * T_ENC,
              (long long)T_ENC * DMODEL, DHEAD,
              (long long)T_ENC * DMODEL, DHEAD,
              BHT, 1.f, false, 0);
        ln_res_kernel<<<M_ENC, 256>>>(xc, att, enc_ln1_g + i * DMODEL, enc_ln1_b + i * DMODEL, x1);
        mgemm(x1, enc_ff_w1 + i * FO1, enc_ff_b1 + i * DFF, h, M_ENC, DFF, DMODEL,
              DMODEL, DFF, DFF, 0,0,0,0,0,0, 1, 1.f, false, 1);
        mgemm(h, enc_ff_w2 + i * FO2, enc_ff_b2 + i * DMODEL, att, M_ENC, DMODEL, DFF,
              DFF, DMODEL, DMODEL, 0,0,0,0,0,0, 1, 1.f, false, 0);
        ln_res_kernel<<<M_ENC, 256>>>(x1, att, enc_ln2_g + i * DMODEL, enc_ln2_b + i * DMODEL, gx);
        xc = gx;
    }

    // -------- decoder --------
    const float* yc = y_in;
    for (int i = 0; i < 2; i++) {
        // masked self-attention: fp32 path (post-softmax -1e10 fill makes PV
        // magnitudes ~1e11; keep full fp32 precision here — it's tiny work)
        mgemm(yc, dec_Wq1 + i * WO, nullptr, q, M_DEC, DMODEL, DMODEL, DMODEL, DMODEL, DMODEL,
              0,0,0,0,0,0, 1, 1.f, false, 0);
        mgemm(yc, dec_Wk1 + i * WO, nullptr, k, M_DEC, DMODEL, DMODEL, DMODEL, DMODEL, DMODEL,
              0,0,0,0,0,0, 1, 1.f, false, 0);
        mgemm(yc, dec_Wv1 + i * WO, nullptr, v, M_DEC, DMODEL, DMODEL, DMODEL, DMODEL, DMODEL,
              0,0,0,0,0,0, 1, 1.f, false, 0);
        attn_scores_kernel<<<dim3(2, 2, BHT), 256>>>(q, k, sc, T_DEC, T_DEC, scale);
        softmax_kernel<<<dim3(T_DEC, BHT), 256>>>(sc, T_DEC, T_DEC, 1);
        attn_pv_kernel<<<dim3(1, 2, BHT), 256>>>(sc, v, att, T_DEC, T_DEC);
        ln_res_kernel<<<M_DEC, 256>>>(yc, att, dec_ln1_g + i * DMODEL, dec_ln1_b + i * DMODEL, y1);

        // cross-attention against encoder output xc
        mgemm(y1, dec_Wq2 + i * WO, nullptr, q, M_DEC, DMODEL, DMODEL, DMODEL, DMODEL, DMODEL,
              0,0,0,0,0,0, 1, 1.f, false, 0);
        mgemm(xc, dec_Wk2 + i * WO, nullptr, k, M_ENC, DMODEL, DMODEL, DMODEL, DMODEL, DMODEL,
              0,0,0,0,0,0, 1, 1.f, false, 0);
        mgemm(xc, dec_Wv2 + i * WO, nullptr, v, M_ENC, DMODEL, DMODEL, DMODEL, DMODEL, DMODEL,
              0,0,0,0,0,0, 1, 1.f, false, 0);
        mgemm(q, k, nullptr, sc, T_DEC, T_ENC, DHEAD, DMODEL, DMODEL, T_ENC,
              (long long)T_DEC * DMODEL, DHEAD,
              (long long)T_ENC * DMODEL, DHEAD,
              8LL * T_DEC * T_ENC, (long long)T_DEC * T_ENC,
              BHT, scale, true, 0);
        softmax_kernel<<<dim3(T_DEC, BHT), 256>>>(sc, T_DEC, T_ENC, 0);
        mgemm(sc, v, nullptr, att, T_DEC, DHEAD, T_ENC, T_ENC, DMODEL, DMODEL,
              8LL * T_DEC * T_ENC, (long long)T_DEC * T_ENC,
              (long long)T_ENC * DMODEL, DHEAD,
              (long long)T_DEC * DMODEL, DHEAD,
              BHT, 1.f, false, 0);
        ln_res_kernel<<<M_DEC, 256>>>(y1, att, dec_ln2_g + i * DMODEL, dec_ln2_b + i * DMODEL, y2);

        // feed-forward
        mgemm(y2, dec_ff_w1 + i * FO1, dec_ff_b1 + i * DFF, h, M_DEC, DFF, DMODEL,
              DMODEL, DFF, DFF, 0,0,0,0,0,0, 1, 1.f, false, 1);
        mgemm(h, dec_ff_w2 + i * FO2, dec_ff_b2 + i * DMODEL, att, M_DEC, DMODEL, DFF,
              DFF, DMODEL, DMODEL, 0,0,0,0,0,0, 1, 1.f, false, 0);
        float* outp = (i == 1) ? (float*)d_out : gy;
        ln_res_kernel<<<M_DEC, 256>>>(y2, att, dec_ln3_g + i * DMODEL, dec_ln3_b + i * DMODEL, outp);
        yc = gy;
    }
}

// round 3
// speedup vs baseline: 3.3098x; 2.2532x over previous
#include <cuda_runtime.h>
#include <cstdint>
#include <cstddef>

// ---------------- problem constants ----------------
#define BATCH   8
#define T_ENC   1024
#define T_DEC   100
#define DMODEL  512
#define NHEAD   8
#define DHEAD   64
#define DFF     2048
#define M_ENC   (BATCH * T_ENC)   // 8192
#define M_DEC   (BATCH * T_DEC)   // 800
#define BHT     (BATCH * NHEAD)   // 64

// ---------------- scratch (device globals; no allocation allowed) ----------------
__device__ float g_q   [M_ENC * DMODEL];
__device__ float g_k   [M_ENC * DMODEL];
__device__ float g_v   [M_ENC * DMODEL];
__device__ float g_att [M_ENC * DMODEL];
__device__ float g_x1  [M_ENC * DMODEL];
__device__ float g_x   [M_ENC * DMODEL];
__device__ float g_h   [M_ENC * DFF];
__device__ float g_scores [BHT * T_DEC * T_DEC];   // decoder self-attn only now
__device__ float g_y1  [M_DEC * DMODEL];
__device__ float g_y2  [M_DEC * DMODEL];
__device__ float g_y   [M_DEC * DMODEL];

__device__ __forceinline__ uint32_t f2tf32(float x) {
    uint32_t t;
    asm("cvt.rna.tf32.f32 %0, %1;" : "=r"(t) : "f"(x));
    return t;
}

__device__ __forceinline__ void mma8(float* c, const uint32_t* a, uint32_t b0, uint32_t b1) {
    asm volatile(
        "mma.sync.aligned.m16n8k8.row.col.f32.tf32.tf32.f32 "
        "{%0,%1,%2,%3}, {%4,%5,%6,%7}, {%8,%9}, {%0,%1,%2,%3};"
        : "+f"(c[0]), "+f"(c[1]), "+f"(c[2]), "+f"(c[3])
        : "r"(a[0]), "r"(a[1]), "r"(a[2]), "r"(a[3]), "r"(b0), "r"(b1));
}

__device__ __forceinline__ void cpasync16(uint32_t smem_dst, const void* gsrc, int bytes) {
    asm volatile("cp.async.ca.shared.global [%0], [%1], 16, %2;"
                 :: "r"(smem_dst), "l"(gsrc), "r"(bytes));
}

// ================= 2-stage cp.async tf32 GEMM =================
// C = A(MxK) @ B(KxN) (+bias) (+relu).  BM=BN=128, BK=32, 256 thr, 8 warps.
// N,K multiples of 128/32; only M may be ragged.
#define GA_STRIDE 36     // 32 + 4
#define GB_STRIDE 132    // 128 + 4
#define GA_STAGE  (128 * GA_STRIDE)
#define GB_STAGE  (32 * GB_STRIDE)
#define GEMM_SMEM ((2 * GA_STAGE + 2 * GB_STAGE) * 4)

template<int RELU>
__global__ __launch_bounds__(256)
void mma_gemm(const float* __restrict__ A, const float* __restrict__ B,
              const float* __restrict__ bias, float* __restrict__ C,
              int M, int N, int K)
{
    extern __shared__ float gsm[];
    float* Asf = gsm;
    float* Bsf = gsm + 2 * GA_STAGE;

    const int tid  = threadIdx.x;
    const int wid  = tid >> 5, lane = tid & 31;
    const int wm   = wid & 1, wn = wid >> 1;
    const int g    = lane >> 2, tig = lane & 3;
    const int m0   = blockIdx.y * 128, n0 = blockIdx.x * 128;

    const uint32_t aBase = (uint32_t)__cvta_generic_to_shared(Asf);
    const uint32_t bBase = (uint32_t)__cvta_generic_to_shared(Bsf);

    float acc[4][4][4];
    #pragma unroll
    for (int i = 0; i < 4; i++)
        #pragma unroll
        for (int j = 0; j < 4; j++)
            #pragma unroll
            for (int c = 0; c < 4; c++) acc[i][j][c] = 0.f;

    auto issue = [&](int s, int k0) {
        #pragma unroll
        for (int i = 0; i < 4; i++) {
            int idx = tid + (i << 8);
            int r = idx >> 3, kk4 = (idx & 7) << 2;
            int m = m0 + r;
            const float* src = A + (size_t)(m < M ? m : 0) * K + k0 + kk4;
            cpasync16(aBase + (s * GA_STAGE + r * GA_STRIDE + kk4) * 4, src, (m < M) ? 16 : 0);
        }
        #pragma unroll
        for (int i = 0; i < 4; i++) {
            int idx = tid + (i << 8);
            int kk = idx >> 5, n4 = (idx & 31) << 2;
            const float* src = B + (size_t)(k0 + kk) * N + n0 + n4;
            cpasync16(bBase + (s * GB_STAGE + kk * GB_STRIDE + n4) * 4, src, 16);
        }
        asm volatile("cp.async.commit_group;");
    };

    const int nk = K >> 5;
    issue(0, 0);

    for (int kt = 0; kt < nk; kt++) {
        const int s = kt & 1;
        if (kt + 1 < nk) {
            issue(s ^ 1, (kt + 1) << 5);
            asm volatile("cp.async.wait_group 1;");
        } else {
            asm volatile("cp.async.wait_group 0;");
        }
        __syncthreads();

        const float* As = Asf + s * GA_STAGE;
        const float* Bs = Bsf + s * GB_STAGE;
        #pragma unroll
        for (int ks = 0; ks < 32; ks += 8) {
            uint32_t af[4][4];
            #pragma unroll
            for (int mi = 0; mi < 4; mi++) {
                int mr = wm * 64 + mi * 16;
                af[mi][0] = f2tf32(As[(mr + g    ) * GA_STRIDE + ks + tig    ]);
                af[mi][1] = f2tf32(As[(mr + g + 8) * GA_STRIDE + ks + tig    ]);
                af[mi][2] = f2tf32(As[(mr + g    ) * GA_STRIDE + ks + tig + 4]);
                af[mi][3] = f2tf32(As[(mr + g + 8) * GA_STRIDE + ks + tig + 4]);
            }
            uint32_t bf[4][2];
            #pragma unroll
            for (int ni = 0; ni < 4; ni++) {
                int nc = wn * 32 + ni * 8 + g;
                bf[ni][0] = f2tf32(Bs[(ks + tig    ) * GB_STRIDE + nc]);
                bf[ni][1] = f2tf32(Bs[(ks + tig + 4) * GB_STRIDE + nc]);
            }
            #pragma unroll
            for (int mi = 0; mi < 4; mi++)
                #pragma unroll
                for (int ni = 0; ni < 4; ni++)
                    mma8(acc[mi][ni], af[mi], bf[ni][0], bf[ni][1]);
        }
        __syncthreads();
    }

    #pragma unroll
    for (int mi = 0; mi < 4; mi++) {
        int mb = m0 + wm * 64 + mi * 16;
        #pragma unroll
        for (int ni = 0; ni < 4; ni++) {
            int nb = n0 + wn * 32 + ni * 8 + 2 * tig;
            #pragma unroll
            for (int c = 0; c < 4; c++) {
                int m = mb + g + ((c & 2) ? 8 : 0);
                int n = nb + (c & 1);
                if (m < M) {
                    float v = acc[mi][ni][c];
                    if (bias) v += bias[n];
                    if (RELU) v = fmaxf(v, 0.f);
                    C[(size_t)m * N + n] = v;
                }
            }
        }
    }
}

// ================= fused flash attention (non-causal, exact) =================
// Per CTA: 128 q-rows x full head. 256 threads = 8 warps, 16 q-rows/warp.
// Loop over 64-row KV tiles: S = scale*Q@K^T (mma), online softmax in c-frag
// registers, P -> smem (tf32), O += P@V (mma). Tk % 64 == 0.
#define FQ_STRIDE 68
#define FLASH_SMEM ((128 * FQ_STRIDE + 64 * FQ_STRIDE + 64 * FQ_STRIDE + 128 * FQ_STRIDE) * 4)

__global__ __launch_bounds__(256)
void flash_attn(const float* __restrict__ Qg, const float* __restrict__ Kg,
                const float* __restrict__ Vg, float* __restrict__ Og,
                int Tq, int Tk, float scale)
{
    extern __shared__ uint32_t fsm[];
    uint32_t* Qs = fsm;                       // [128][68]
    uint32_t* Ks = Qs + 128 * FQ_STRIDE;      // [64][68]  (n-major: row = kv)
    uint32_t* Vs = Ks + 64 * FQ_STRIDE;       // [64][68]  (k-major: row = kv, col = d)
    uint32_t* Ps = Vs + 64 * FQ_STRIDE;       // [128][68]

    const int bh = blockIdx.y;
    const int b = bh >> 3, h = bh & 7;
    const int q0 = blockIdx.x * 128;
    const int tid = threadIdx.x;
    const int wid = tid >> 5, lane = tid & 31;
    const int g = lane >> 2, tig = lane & 3;
    const int mr = wid * 16;

    const float* qp = Qg + (size_t)b * Tq * DMODEL + h * DHEAD;
    const float* kp = Kg + (size_t)b * Tk * DMODEL + h * DHEAD;
    const float* vp = Vg + (size_t)b * Tk * DMODEL + h * DHEAD;

    // load + convert Q tile
    #pragma unroll
    for (int i = 0; i < 8; i++) {
        int idx = tid + (i << 8);
        int r = idx >> 4, d4 = (idx & 15) << 2;
        int q = q0 + r;
        float4 v = (q < Tq) ? *(const float4*)(qp + (size_t)q * DMODEL + d4)
                            : make_float4(0.f, 0.f, 0.f, 0.f);
        uint32_t* dst = &Qs[r * FQ_STRIDE + d4];
        dst[0] = f2tf32(v.x); dst[1] = f2tf32(v.y);
        dst[2] = f2tf32(v.z); dst[3] = f2tf32(v.w);
    }

    float o[8][4];
    #pragma unroll
    for (int ni = 0; ni < 8; ni++)
        #pragma unroll
        for (int c = 0; c < 4; c++) o[ni][c] = 0.f;
    float m0 = -1e30f, m1 = -1e30f, l0 = 0.f, l1 = 0.f;

    for (int kt = 0; kt < Tk; kt += 64) {
        __syncthreads();
        #pragma unroll
        for (int i = 0; i < 4; i++) {
            int idx = tid + (i << 8);
            int r = idx >> 4, d4 = (idx & 15) << 2;
            float4 kv = *(const float4*)(kp + (size_t)(kt + r) * DMODEL + d4);
            uint32_t* dk = &Ks[r * FQ_STRIDE + d4];
            dk[0] = f2tf32(kv.x); dk[1] = f2tf32(kv.y);
            dk[2] = f2tf32(kv.z); dk[3] = f2tf32(kv.w);
            float4 vv = *(const float4*)(vp + (size_t)(kt + r) * DMODEL + d4);
            uint32_t* dv = &Vs[r * FQ_STRIDE + d4];
            dv[0] = f2tf32(vv.x); dv[1] = f2tf32(vv.y);
            dv[2] = f2tf32(vv.z); dv[3] = f2tf32(vv.w);
        }
        __syncthreads();

        // ---- S = Q @ K^T ----
        float s[8][4];
        #pragma unroll
        for (int ni = 0; ni < 8; ni++)
            #pragma unroll
            for (int c = 0; c < 4; c++) s[ni][c] = 0.f;
        #pragma unroll
        for (int ks = 0; ks < 64; ks += 8) {
            uint32_t af[4];
            af[0] = Qs[(mr + g    ) * FQ_STRIDE + ks + tig    ];
            af[1] = Qs[(mr + g + 8) * FQ_STRIDE + ks + tig    ];
            af[2] = Qs[(mr + g    ) * FQ_STRIDE + ks + tig + 4];
            af[3] = Qs[(mr + g + 8) * FQ_STRIDE + ks + tig + 4];
            #pragma unroll
            for (int ni = 0; ni < 8; ni++) {
                uint32_t b0 = Ks[(ni * 8 + g) * FQ_STRIDE + ks + tig    ];
                uint32_t b1 = Ks[(ni * 8 + g) * FQ_STRIDE + ks + tig + 4];
                mma8(s[ni], af, b0, b1);
            }
        }

        // ---- online softmax ----
        float tmax0 = -1e30f, tmax1 = -1e30f;
        #pragma unroll
        for (int ni = 0; ni < 8; ni++) {
            #pragma unroll
            for (int c = 0; c < 4; c++) s[ni][c] *= scale;
            tmax0 = fmaxf(tmax0, fmaxf(s[ni][0], s[ni][1]));
            tmax1 = fmaxf(tmax1, fmaxf(s[ni][2], s[ni][3]));
        }
        #pragma unroll
        for (int off = 1; off <= 2; off <<= 1) {
            tmax0 = fmaxf(tmax0, __shfl_xor_sync(0xffffffffu, tmax0, off));
            tmax1 = fmaxf(tmax1, __shfl_xor_sync(0xffffffffu, tmax1, off));
        }
        const float mn0 = fmaxf(m0, tmax0), mn1 = fmaxf(m1, tmax1);
        const float a0 = expf(m0 - mn0), a1 = expf(m1 - mn1);
        float rs0 = 0.f, rs1 = 0.f;
        #pragma unroll
        for (int ni = 0; ni < 8; ni++) {
            float p0 = expf(s[ni][0] - mn0);
            float p1 = expf(s[ni][1] - mn0);
            float p2 = expf(s[ni][2] - mn1);
            float p3 = expf(s[ni][3] - mn1);
            rs0 += p0 + p1; rs1 += p2 + p3;
            int col = ni * 8 + 2 * tig;
            Ps[(mr + g    ) * FQ_STRIDE + col    ] = f2tf32(p0);
            Ps[(mr + g    ) * FQ_STRIDE + col + 1] = f2tf32(p1);
            Ps[(mr + g + 8) * FQ_STRIDE + col    ] = f2tf32(p2);
            Ps[(mr + g + 8) * FQ_STRIDE + col + 1] = f2tf32(p3);
        }
        #pragma unroll
        for (int off = 1; off <= 2; off <<= 1) {
            rs0 += __shfl_xor_sync(0xffffffffu, rs0, off);
            rs1 += __shfl_xor_sync(0xffffffffu, rs1, off);
        }
        l0 = l0 * a0 + rs0; l1 = l1 * a1 + rs1;
        m0 = mn0; m1 = mn1;
        #pragma unroll
        for (int ni = 0; ni < 8; ni++) {
            o[ni][0] *= a0; o[ni][1] *= a0;
            o[ni][2] *= a1; o[ni][3] *= a1;
        }
        __syncwarp();

        // ---- O += P @ V ----
        #pragma unroll
        for (int ks = 0; ks < 64; ks += 8) {
            uint32_t af[4];
            af[0] = Ps[(mr + g    ) * FQ_STRIDE + ks + tig    ];
            af[1] = Ps[(mr + g + 8) * FQ_STRIDE + ks + tig    ];
            af[2] = Ps[(mr + g    ) * FQ_STRIDE + ks + tig + 4];
            af[3] = Ps[(mr + g + 8) * FQ_STRIDE + ks + tig + 4];
            #pragma unroll
            for (int ni = 0; ni < 8; ni++) {
                uint32_t b0 = Vs[(ks + tig    ) * FQ_STRIDE + ni * 8 + g];
                uint32_t b1 = Vs[(ks + tig + 4) * FQ_STRIDE + ni * 8 + g];
                mma8(o[ni], af, b0, b1);
            }
        }
    }

    // ---- epilogue: normalize + store ----
    const float i0 = 1.f / l0, i1 = 1.f / l1;
    #pragma unroll
    for (int ni = 0; ni < 8; ni++) {
        int col = h * DHEAD + ni * 8 + 2 * tig;
        int r0 = q0 + mr + g, r1 = r0 + 8;
        if (r0 < Tq) {
            Og[(size_t)(b * Tq + r0) * DMODEL + col    ] = o[ni][0] * i0;
            Og[(size_t)(b * Tq + r0) * DMODEL + col + 1] = o[ni][1] * i0;
        }
        if (r1 < Tq) {
            Og[(size_t)(b * Tq + r1) * DMODEL + col    ] = o[ni][2] * i1;
            Og[(size_t)(b * Tq + r1) * DMODEL + col + 1] = o[ni][3] * i1;
        }
    }
}

// ---------------- fp32 attention kernels (decoder self-attention only) ----------------
__global__ void attn_scores_kernel(const float* __restrict__ Q, const float* __restrict__ Kb,
                                   float* __restrict__ S, int Tq, int Tk, float scale) {
    __shared__ float Qs[64][65];
    __shared__ float Ks[64][65];
    const int bh = blockIdx.z;
    const int b = bh >> 3, h = bh & 7;
    const float* qp = Q + (size_t)b * Tq * DMODEL + h * DHEAD;
    const float* kp = Kb + (size_t)b * Tk * DMODEL + h * DHEAD;
    float* sp = S + (size_t)bh * Tq * Tk;
    const int q0 = blockIdx.y * 64, k0 = blockIdx.x * 64;
    const int tid = threadIdx.x;

    #pragma unroll
    for (int i = 0; i < 16; i++) {
        int idx = tid + i * 256;
        int r = idx >> 6, d = idx & 63;
        Qs[r][d] = (q0 + r < Tq) ? qp[(size_t)(q0 + r) * DMODEL + d] : 0.f;
    }
    #pragma unroll
    for (int i = 0; i < 16; i++) {
        int idx = tid + i * 256;
        int r = idx >> 6, d = idx & 63;
        Ks[r][d] = (k0 + r < Tk) ? kp[(size_t)(k0 + r) * DMODEL + d] : 0.f;
    }
    __syncthreads();

    const int tx = tid & 15, ty = tid >> 4;
    float acc[4][4] = {};
    #pragma unroll
    for (int d = 0; d < 64; d++) {
        float a[4], b2[4];
        #pragma unroll
        for (int i = 0; i < 4; i++) a[i] = Qs[ty * 4 + i][d];
        #pragma unroll
        for (int j = 0; j < 4; j++) b2[j] = Ks[tx * 4 + j][d];
        #pragma unroll
        for (int i = 0; i < 4; i++)
            #pragma unroll
            for (int j = 0; j < 4; j++)
                acc[i][j] += a[i] * b2[j];
    }
    #pragma unroll
    for (int i = 0; i < 4; i++) {
        int q = q0 + ty * 4 + i;
        if (q >= Tq) continue;
        #pragma unroll
        for (int j = 0; j < 4; j++) {
            int k = k0 + tx * 4 + j;
            if (k < Tk) sp[(size_t)q * Tk + k] = acc[i][j] * scale;
        }
    }
}

__global__ void attn_pv_kernel(const float* __restrict__ P, const float* __restrict__ V,
                               float* __restrict__ O, int Tq, int Tk) {
    __shared__ float Ps[64][33];
    __shared__ float Vs[32][65];
    const int bh = blockIdx.z;
    const int b = bh >> 3, h = bh & 7;
    const float* pp = P + (size_t)bh * Tq * Tk;
    const float* vp = V + (size_t)b * Tk * DMODEL + h * DHEAD;
    const int q0 = blockIdx.y * 64;
    const int tid = threadIdx.x;
    const int tx = tid & 15, ty = tid >> 4;
    float acc[4][4] = {};

    for (int k0 = 0; k0 < Tk; k0 += 32) {
        #pragma unroll
        for (int i = 0; i < 8; i++) {
            int idx = tid + i * 256;
            int r = idx >> 5, kk = idx & 31;
            int q = q0 + r, k = k0 + kk;
            Ps[r][kk] = (q < Tq && k < Tk) ? pp[(size_t)q * Tk + k] : 0.f;
        }
        #pragma unroll
        for (int i = 0; i < 8; i++) {
            int idx = tid + i * 256;
            int kk = idx >> 6, d = idx & 63;
            int k = k0 + kk;
            Vs[kk][d] = (k < Tk) ? vp[(size_t)k * DMODEL + d] : 0.f;
        }
        __syncthreads();
        #pragma unroll
        for (int kk = 0; kk < 32; kk++) {
            float a[4], b2[4];
            #pragma unroll
            for (int i = 0; i < 4; i++) a[i] = Ps[ty * 4 + i][kk];
            #pragma unroll
            for (int j = 0; j < 4; j++) b2[j] = Vs[kk][tx * 4 + j];
            #pragma unroll
            for (int i = 0; i < 4; i++)
                #pragma unroll
                for (int j = 0; j < 4; j++)
                    acc[i][j] += a[i] * b2[j];
        }
        __syncthreads();
    }

    #pragma unroll
    for (int i = 0; i < 4; i++) {
        int q = q0 + ty * 4 + i;
        if (q >= Tq) continue;
        #pragma unroll
        for (int j = 0; j < 4; j++)
            O[(size_t)(b * Tq + q) * DMODEL + h * DHEAD + tx * 4 + j] = acc[i][j];
    }
}

// ---------------- softmax (decoder self only; post-softmax -1e10 causal fill) ----------------
__global__ void softmax_kernel(float* __restrict__ S, int Tq, int Tk, int causal) {
    const int q = blockIdx.x, bh = blockIdx.y, tid = threadIdx.x;
    float* row = S + ((size_t)bh * Tq + q) * Tk;
    __shared__ float redm[8];
    __shared__ float reds[8];

    float r[4];
    float m = -1e30f;
    #pragma unroll
    for (int i = 0; i < 4; i++) {
        int k = tid + (i << 8);
        r[i] = (k < Tk) ? row[k] : -1e30f;
        m = fmaxf(m, r[i]);
    }
    #pragma unroll
    for (int o = 16; o; o >>= 1) m = fmaxf(m, __shfl_xor_sync(0xffffffffu, m, o));
    if ((tid & 31) == 0) redm[tid >> 5] = m;
    __syncthreads();
    m = redm[0];
    #pragma unroll
    for (int i = 1; i < 8; i++) m = fmaxf(m, redm[i]);

    float s = 0.f;
    #pragma unroll
    for (int i = 0; i < 4; i++) {
        r[i] = expf(r[i] - m);
        s += r[i];
    }
    #pragma unroll
    for (int o = 16; o; o >>= 1) s += __shfl_xor_sync(0xffffffffu, s, o);
    if ((tid & 31) == 0) reds[tid >> 5] = s;
    __syncthreads();
    s = 0.f;
    #pragma unroll
    for (int i = 0; i < 8; i++) s += reds[i];
    const float inv = 1.f / s;

    #pragma unroll
    for (int i = 0; i < 4; i++) {
        int k = tid + (i << 8);
        if (k < Tk) {
            float p = r[i] * inv;
            if (causal && k > q) p = -1e10f;
            row[k] = p;
        }
    }
}

// ---------------- fused residual + LayerNorm over D=512 ----------------
__global__ void ln_res_kernel(const float* __restrict__ A, const float* __restrict__ Bv,
                              const float* __restrict__ g, const float* __restrict__ be,
                              float* __restrict__ O) {
    const int row = blockIdx.x;
    const float* a = A + (size_t)row * DMODEL;
    const float* b = Bv + (size_t)row * DMODEL;
    __shared__ float red[256];
    const int tid = threadIdx.x;

    float v0 = a[tid] + b[tid];
    float v1 = a[tid + 256] + b[tid + 256];

    red[tid] = v0 + v1; __syncthreads();
    for (int s = 128; s > 0; s >>= 1) { if (tid < s) red[tid] += red[tid + s]; __syncthreads(); }
    const float mean = red[0] * (1.f / DMODEL); __syncthreads();

    float d0 = v0 - mean, d1 = v1 - mean;
    red[tid] = d0 * d0 + d1 * d1; __syncthreads();
    for (int s = 128; s > 0; s >>= 1) { if (tid < s) red[tid] += red[tid + s]; __syncthreads(); }
    const float inv = rsqrtf(red[0] * (1.f / DMODEL) + 1e-5f);

    O[(size_t)row * DMODEL + tid]       = d0 * inv * g[tid]       + be[tid];
    O[(size_t)row * DMODEL + tid + 256] = d1 * inv * g[tid + 256] + be[tid + 256];
}

// ---------------- host orchestration ----------------
static inline void mgemm(const float* A, const float* B, const float* bias, float* C,
                         int M, int N, int K, int relu) {
    dim3 grid(N / 128, (M + 127) / 128);
    if (relu)
        mma_gemm<1><<<grid, 256, GEMM_SMEM>>>(A, B, bias, C, M, N, K);
    else
        mma_gemm<0><<<grid, 256, GEMM_SMEM>>>(A, B, bias, C, M, N, K);
}

template <typename T>
static inline float* sym(T& s) {
    void* p = nullptr;
    cudaGetSymbolAddress(&p, s);
    return (float*)p;
}

extern "C" void kernel_launch(void* const* d_in, const int* in_sizes, int n_in,
                              void* d_out, int out_size) {
    (void)in_sizes; (void)n_in; (void)out_size;

    cudaFuncSetAttribute(mma_gemm<0>, cudaFuncAttributeMaxDynamicSharedMemorySize, GEMM_SMEM);
    cudaFuncSetAttribute(mma_gemm<1>, cudaFuncAttributeMaxDynamicSharedMemorySize, GEMM_SMEM);
    cudaFuncSetAttribute(flash_attn, cudaFuncAttributeMaxDynamicSharedMemorySize, FLASH_SMEM);

    const float* x_in      = (const float*)d_in[0];
    const float* y_in      = (const float*)d_in[1];
    const float* enc_Wq    = (const float*)d_in[2];
    const float* enc_Wk    = (const float*)d_in[3];
    const float* enc_Wv    = (const float*)d_in[4];
    const float* enc_ff_w1 = (const float*)d_in[5];
    const float* enc_ff_b1 = (const float*)d_in[6];
    const float* enc_ff_w2 = (const float*)d_in[7];
    const float* enc_ff_b2 = (const float*)d_in[8];
    const float* enc_ln1_g = (const float*)d_in[9];
    const float* enc_ln1_b = (const float*)d_in[10];
    const float* enc_ln2_g = (const float*)d_in[11];
    const float* enc_ln2_b = (const float*)d_in[12];
    const float* dec_Wq1   = (const float*)d_in[13];
    const float* dec_Wk1   = (const float*)d_in[14];
    const float* dec_Wv1   = (const float*)d_in[15];
    const float* dec_Wq2   = (const float*)d_in[16];
    const float* dec_Wk2   = (const float*)d_in[17];
    const float* dec_Wv2   = (const float*)d_in[18];
    const float* dec_ff_w1 = (const float*)d_in[19];
    const float* dec_ff_b1 = (const float*)d_in[20];
    const float* dec_ff_w2 = (const float*)d_in[21];
    const float* dec_ff_b2 = (const float*)d_in[22];
    const float* dec_ln1_g = (const float*)d_in[23];
    const float* dec_ln1_b = (const float*)d_in[24];
    const float* dec_ln2_g = (const float*)d_in[25];
    const float* dec_ln2_b = (const float*)d_in[26];
    const float* dec_ln3_g = (const float*)d_in[27];
    const float* dec_ln3_b = (const float*)d_in[28];

    float* q   = sym(g_q);
    float* k   = sym(g_k);
    float* v   = sym(g_v);
    float* att = sym(g_att);
    float* x1  = sym(g_x1);
    float* gx  = sym(g_x);
    float* h   = sym(g_h);
    float* sc  = sym(g_scores);
    float* y1  = sym(g_y1);
    float* y2  = sym(g_y2);
    float* gy  = sym(g_y);

    const float scale = 0.125f;  // 1/sqrt(64)
    const long long WO = DMODEL * DMODEL;
    const long long FO1 = DMODEL * DFF;
    const long long FO2 = DFF * DMODEL;

    // -------- encoder --------
    const float* xc = x_in;
    for (int i = 0; i < 2; i++) {
        mgemm(xc, enc_Wq + i * WO, nullptr, q, M_ENC, DMODEL, DMODEL, 0);
        mgemm(xc, enc_Wk + i * WO, nullptr, k, M_ENC, DMODEL, DMODEL, 0);
        mgemm(xc, enc_Wv + i * WO, nullptr, v, M_ENC, DMODEL, DMODEL, 0);
        flash_attn<<<dim3(T_ENC / 128, BHT), 256, FLASH_SMEM>>>(q, k, v, att, T_ENC, T_ENC, scale);
        ln_res_kernel<<<M_ENC, 256>>>(xc, att, enc_ln1_g + i * DMODEL, enc_ln1_b + i * DMODEL, x1);
        mgemm(x1, enc_ff_w1 + i * FO1, enc_ff_b1 + i * DFF, h, M_ENC, DFF, DMODEL, 1);
        mgemm(h, enc_ff_w2 + i * FO2, enc_ff_b2 + i * DMODEL, att, M_ENC, DMODEL, DFF, 0);
        ln_res_kernel<<<M_ENC, 256>>>(x1, att, enc_ln2_g + i * DMODEL, enc_ln2_b + i * DMODEL, gx);
        xc = gx;
    }

    // -------- decoder --------
    const float* yc = y_in;
    for (int i = 0; i < 2; i++) {
        // masked self-attention: exact fp32 path (post-softmax -1e10 fill)
        mgemm(yc, dec_Wq1 + i * WO, nullptr, q, M_DEC, DMODEL, DMODEL, 0);
        mgemm(yc, dec_Wk1 + i * WO, nullptr, k, M_DEC, DMODEL, DMODEL, 0);
        mgemm(yc, dec_Wv1 + i * WO, nullptr, v, M_DEC, DMODEL, DMODEL, 0);
        attn_scores_kernel<<<dim3(2, 2, BHT), 256>>>(q, k, sc, T_DEC, T_DEC, scale);
        softmax_kernel<<<dim3(T_DEC, BHT), 256>>>(sc, T_DEC, T_DEC, 1);
        attn_pv_kernel<<<dim3(1, 2, BHT), 256>>>(sc, v, att, T_DEC, T_DEC);
        ln_res_kernel<<<M_DEC, 256>>>(yc, att, dec_ln1_g + i * DMODEL, dec_ln1_b + i * DMODEL, y1);

        // cross-attention (non-causal -> flash)
        mgemm(y1, dec_Wq2 + i * WO, nullptr, q, M_DEC, DMODEL, DMODEL, 0);
        mgemm(xc, dec_Wk2 + i * WO, nullptr, k, M_ENC, DMODEL, DMODEL, 0);
        mgemm(xc, dec_Wv2 + i * WO, nullptr, v, M_ENC, DMODEL, DMODEL, 0);
        flash_attn<<<dim3(1, BHT), 256, FLASH_SMEM>>>(q, k, v, att, T_DEC, T_ENC, scale);
        ln_res_kernel<<<M_DEC, 256>>>(y1, att, dec_ln2_g + i * DMODEL, dec_ln2_b + i * DMODEL, y2);

        // feed-forward
        mgemm(y2, dec_ff_w1 + i * FO1, dec_ff_b1 + i * DFF, h, M_DEC, DFF, DMODEL, 1);
        mgemm(h, dec_ff_w2 + i * FO2, dec_ff_b2 + i * DMODEL, att, M_DEC, DMODEL, DFF, 0);
        float* outp = (i == 1) ? (float*)d_out : gy;
        ln_res_kernel<<<M_DEC, 256>>>(y2, att, dec_ln3_g + i * DMODEL, dec_ln3_b + i * DMODEL, outp);
        yc = gy;
    }
}